// round 8
// baseline (speedup 1.0000x reference)
#include <cuda_runtime.h>
#include <cstdint>

// Problem constants
#define N_IMG   64
#define C_IN    64
#define H_IN    128
#define W_IN    128
#define KH      3
#define KW      3
#define OH      126
#define OW      126

// Tiling: 64 wide x 32 tall output tile per block
#define TILE_W  64
#define TILE_H  32
#define SM_W    68            // padded width: 17 float4 chunks per row
#define SM_H    34            // TILE_H + KH - 1
#define THREADS 256
#define STAGES  3
#define KER_ELEMS (C_IN * KH * KW)   // 576

#define CHUNKS_PER_ROW 17
#define TOTAL_CHUNKS   (SM_H * CHUNKS_PER_ROW)   // 578
#define CHUNK_ITERS    ((TOTAL_CHUNKS + THREADS - 1) / THREADS)  // 3

__device__ __forceinline__ uint32_t smem_u32(const void* p) {
    uint32_t a;
    asm("{ .reg .u64 t; cvta.to.shared.u64 t, %1; cvt.u32.u64 %0, t; }" : "=r"(a) : "l"(p));
    return a;
}
__device__ __forceinline__ void cp_async16(uint32_t smem_addr, const void* gptr) {
    asm volatile("cp.async.cg.shared.global [%0], [%1], 16;\n" :: "r"(smem_addr), "l"(gptr));
}
__device__ __forceinline__ void cp_commit() {
    asm volatile("cp.async.commit_group;\n" ::: "memory");
}
__device__ __forceinline__ void cp_wait_1() {
    asm volatile("cp.async.wait_group 1;\n" ::: "memory");
}

__global__ __launch_bounds__(THREADS, 4)
void imagewise_conv2d_kernel(const float* __restrict__ images,
                             const float* __restrict__ kernels,
                             float* __restrict__ out)
{
    __shared__ float s_img[STAGES][SM_H * SM_W];  // 3 * 34*68*4 = 27744 B
    __shared__ float s_ker[KER_ELEMS];            // 2304 B

    const int tid = threadIdx.x;
    const int n   = blockIdx.z;
    const int ox0 = blockIdx.x * TILE_W;
    const int oy0 = blockIdx.y * TILE_H;

    // Stage this sample's full kernel stack once (consumed after first barrier)
    for (int i = tid; i < KER_ELEMS; i += THREADS) {
        s_ker[i] = kernels[n * KER_ELEMS + i];
    }

    const float* img_n = images + (size_t)n * C_IN * H_IN * W_IN;

    // ---- Per-thread cp.async chunk addresses (channel-invariant) ----
    // Clamped chunks only fill smem cells consumed by never-stored outputs.
    int      g_off[CHUNK_ITERS];
    uint32_t s_off[CHUNK_ITERS];
    bool     valid[CHUNK_ITERS];
#pragma unroll
    for (int it = 0; it < CHUNK_ITERS; ++it) {
        int j = tid + it * THREADS;
        valid[it] = (j < TOTAL_CHUNKS);
        if (!valid[it]) j = TOTAL_CHUNKS - 1;
        int row = j / CHUNKS_PER_ROW;
        int k   = j - row * CHUNKS_PER_ROW;
        int gy  = oy0 + row; if (gy > H_IN - 1) gy = H_IN - 1;
        int gx  = ox0 + 4 * k; if (gx > W_IN - 4) gx = W_IN - 4;
        g_off[it] = gy * W_IN + gx;
        s_off[it] = (uint32_t)((row * SM_W + 4 * k) * sizeof(float));
    }
    uint32_t s_base[STAGES];
#pragma unroll
    for (int s = 0; s < STAGES; ++s) s_base[s] = smem_u32(&s_img[s][0]);

    // ---- Compute mapping: 4 cols x 2 rows per thread ----
    const int tx   = tid & 15;       // col group: cols 4tx..4tx+3
    const int tyg  = tid >> 4;       // row group: rows 2tyg..2tyg+1
    const int col0 = 4 * tx;
    const int row0 = 2 * tyg;

    float acc[2][4];
#pragma unroll
    for (int o = 0; o < 2; ++o)
#pragma unroll
        for (int cc = 0; cc < 4; ++cc) acc[o][cc] = 0.0f;

    // ---- Prologue: prefetch channels 0 and 1 ----
#pragma unroll
    for (int s = 0; s < STAGES - 1; ++s) {
        const float* img_c = img_n + (size_t)s * H_IN * W_IN;
#pragma unroll
        for (int it = 0; it < CHUNK_ITERS; ++it)
            if (valid[it]) cp_async16(s_base[s] + s_off[it], img_c + g_off[it]);
        cp_commit();
    }

    // ---- Main loop: depth-3 pipeline, ONE barrier per channel ----
    int cur = 0;   // buffer index of channel c
    for (int c = 0; c < C_IN; ++c) {
        cp_wait_1();       // own chunks of stage c complete (<=1 group outstanding)
        __syncthreads();   // stage c visible chip-wide; all threads done compute(c-1)
                           //  -> licenses overwrite of buf[(c-1)%3] below

        // Prefetch channel c+2 into buf[(c+2)%3] == buf[(c-1)%3]
        {
            int cn = c + STAGES - 1;
            int tgt = (cur == 0) ? (STAGES - 1) : (cur - 1);
            if (cn < C_IN) {
                const float* img_c = img_n + (size_t)cn * H_IN * W_IN;
#pragma unroll
                for (int it = 0; it < CHUNK_ITERS; ++it)
                    if (valid[it]) cp_async16(s_base[tgt] + s_off[it], img_c + g_off[it]);
            }
            cp_commit();   // empty group near the tail is legal and keeps counts aligned
        }

        // Channel c's 3x3 weights (broadcast LDS)
        const float w0 = s_ker[c * 9 + 0], w1 = s_ker[c * 9 + 1], w2 = s_ker[c * 9 + 2];
        const float w3 = s_ker[c * 9 + 3], w4 = s_ker[c * 9 + 4], w5 = s_ker[c * 9 + 5];
        const float w6 = s_ker[c * 9 + 6], w7 = s_ker[c * 9 + 7], w8 = s_ker[c * 9 + 8];

        const float* colp = s_img[cur] + row0 * SM_W + col0;
#pragma unroll
        for (int r = 0; r < 2 + KH - 1; ++r) {   // 4 input rows
            float4 f4 = *(const float4*)(colp + r * SM_W);
            float2 f2 = *(const float2*)(colp + r * SM_W + 4);
            float x[6] = {f4.x, f4.y, f4.z, f4.w, f2.x, f2.y};
#pragma unroll
            for (int o = 0; o < 2; ++o) {
                int ky = r - o;
                if (ky >= 0 && ky < KH) {
                    float wa = (ky == 0) ? w0 : (ky == 1) ? w3 : w6;
                    float wb = (ky == 0) ? w1 : (ky == 1) ? w4 : w7;
                    float wc = (ky == 0) ? w2 : (ky == 1) ? w5 : w8;
#pragma unroll
                    for (int cc = 0; cc < 4; ++cc) {
                        acc[o][cc] = fmaf(x[cc + 0], wa,
                                     fmaf(x[cc + 1], wb,
                                     fmaf(x[cc + 2], wc, acc[o][cc])));
                    }
                }
            }
        }

        cur = (cur == STAGES - 1) ? 0 : cur + 1;
    }

    // ---- Store valid outputs ----
    float* out_n = out + (size_t)n * OH * OW;
#pragma unroll
    for (int o = 0; o < 2; ++o) {
        int gy = oy0 + row0 + o;
        if (gy < OH) {
#pragma unroll
            for (int cc = 0; cc < 4; ++cc) {
                int gx = ox0 + col0 + cc;
                if (gx < OW) {
                    out_n[gy * OW + gx] = acc[o][cc];
                }
            }
        }
    }
}

extern "C" void kernel_launch(void* const* d_in, const int* in_sizes, int n_in,
                              void* d_out, int out_size)
{
    const float* images  = (const float*)d_in[0];
    const float* kernels = (const float*)d_in[1];
    float* out = (float*)d_out;

    dim3 grid((OW + TILE_W - 1) / TILE_W,   // 2
              (OH + TILE_H - 1) / TILE_H,   // 4
              N_IMG);                       // 64  -> 512 CTAs
    imagewise_conv2d_kernel<<<grid, THREADS>>>(images, kernels, out);
}